// round 7
// baseline (speedup 1.0000x reference)
#include <cuda_runtime.h>
#include <cuda_bf16.h>
#include <math.h>
#include <stdint.h>
#include <stddef.h>

#define NMESH 10242
#define NGRID 65160
#define NEDGES 195480
#define DDIM 512
#define NOUT 471

// GEMM tiling: CTA 128x256, K-chunk 32 bf16; 8 warps of 64x64
#define BM 128
#define BN 256
#define BK 32
#define NTHR 256

// Smem: [0,512) sSrc, [512,1024) sDst, buffers at 1024
// buffer: Ahi[128][40bf16] (10240B), Alo +10240, Bhi[256][40] @20480, Blo @40960
#define SMROW 80              // padded row stride bytes (32 bf16 = 64B + 16B pad)
#define SM_ALO 10240
#define SM_BHI 20480
#define SM_BLO 40960
#define SM_BUFSZ 61440
#define SM_BUFS 1024
#define SM_TOTAL (SM_BUFS + 2 * SM_BUFSZ)

// ---------------------------------------------------------------------------
// Scratch (device globals — no dynamic allocation allowed)
// ---------------------------------------------------------------------------
__device__ float g_e0[(size_t)NEDGES * DDIM];
__device__ float g_h[(size_t)NEDGES * DDIM];
__device__ float g_agg[(size_t)NGRID * DDIM];
__device__ float g_gridnew[(size_t)NGRID * DDIM];

// Pre-transposed / pre-split weights: [N=512 rows][K] row-major bf16
#define OFF_EMBW1  0u         /* K=512  */
#define OFF_EDGEW0 262144u    /* K=1536 */
#define OFF_EDGEW1 1048576u   /* K=512  */
#define OFF_NODEW0 1310720u   /* K=1024 */
#define OFF_NODEW1 1835008u   /* K=512  */
#define OFF_OUTW0  2097152u   /* K=512  */
#define OFF_OUTW1  2359296u   /* K=512, padded from 471 cols */
#define WT_TOTAL   2621440u
__device__ __nv_bfloat16 g_wThi[WT_TOTAL];
__device__ __nv_bfloat16 g_wTlo[WT_TOTAL];

// ---------------------------------------------------------------------------
// Helpers
// ---------------------------------------------------------------------------
__device__ __forceinline__ uint32_t smem_u32(const void* p) {
    uint32_t a;
    asm("{ .reg .u64 t; cvta.to.shared.u64 t, %1; cvt.u32.u64 %0, t; }"
        : "=r"(a) : "l"(p));
    return a;
}
__device__ __forceinline__ void cpasync16(uint32_t dst, const void* src) {
    asm volatile("cp.async.cg.shared.global [%0], [%1], 16;"
                 :: "r"(dst), "l"(src) : "memory");
}
__device__ __forceinline__ void cp_commit() {
    asm volatile("cp.async.commit_group;" ::: "memory");
}
__device__ __forceinline__ void cp_wait_all() {
    asm volatile("cp.async.wait_group 0;" ::: "memory");
}
__device__ __forceinline__ void ldsm4(uint32_t* r, uint32_t addr) {
    asm volatile("ldmatrix.sync.aligned.m8n8.x4.shared.b16 {%0,%1,%2,%3}, [%4];"
                 : "=r"(r[0]), "=r"(r[1]), "=r"(r[2]), "=r"(r[3]) : "r"(addr));
}
__device__ __forceinline__ void mma_bf16(float* c, const uint32_t* a, const uint32_t* b) {
    asm volatile(
        "mma.sync.aligned.m16n8k16.row.col.f32.bf16.bf16.f32 "
        "{%0,%1,%2,%3}, {%4,%5,%6,%7}, {%8,%9}, {%0,%1,%2,%3};"
        : "+f"(c[0]), "+f"(c[1]), "+f"(c[2]), "+f"(c[3])
        : "r"(a[0]), "r"(a[1]), "r"(a[2]), "r"(a[3]), "r"(b[0]), "r"(b[1]));
}
__device__ __forceinline__ void split4(float4 v, uint2& H, uint2& L) {
    __nv_bfloat16 hx = __float2bfloat16(v.x), hy = __float2bfloat16(v.y);
    __nv_bfloat16 hz = __float2bfloat16(v.z), hw = __float2bfloat16(v.w);
    __nv_bfloat16 lx = __float2bfloat16(v.x - __bfloat162float(hx));
    __nv_bfloat16 ly = __float2bfloat16(v.y - __bfloat162float(hy));
    __nv_bfloat16 lz = __float2bfloat16(v.z - __bfloat162float(hz));
    __nv_bfloat16 lw = __float2bfloat16(v.w - __bfloat162float(hw));
    H.x = (uint32_t)__bfloat16_as_ushort(hx) | ((uint32_t)__bfloat16_as_ushort(hy) << 16);
    H.y = (uint32_t)__bfloat16_as_ushort(hz) | ((uint32_t)__bfloat16_as_ushort(hw) << 16);
    L.x = (uint32_t)__bfloat16_as_ushort(lx) | ((uint32_t)__bfloat16_as_ushort(ly) << 16);
    L.y = (uint32_t)__bfloat16_as_ushort(lz) | ((uint32_t)__bfloat16_as_ushort(lw) << 16);
}
__device__ __forceinline__ float silu_f(float v) {
    return __fdividef(v, 1.0f + __expf(-v));
}

// ---------------------------------------------------------------------------
// Small kernels
// ---------------------------------------------------------------------------
__global__ void emb_l1_kernel(const float* __restrict__ attrs,
                              const float* __restrict__ w0,
                              const float* __restrict__ b0,
                              float* __restrict__ h0) {
    size_t idx = (size_t)blockIdx.x * blockDim.x + threadIdx.x;
    if (idx >= (size_t)NEDGES * DDIM) return;
    int r = (int)(idx >> 9);
    int c = (int)(idx & 511);
    float v = b0[c];
#pragma unroll
    for (int j = 0; j < 4; j++)
        v = fmaf(attrs[r * 4 + j], w0[j * DDIM + c], v);
    h0[idx] = silu_f(v);
}

__global__ void zero_kernel(float4* __restrict__ p, size_t n4) {
    size_t i = (size_t)blockIdx.x * blockDim.x + threadIdx.x;
    if (i < n4) p[i] = make_float4(0.f, 0.f, 0.f, 0.f);
}

// W [K, Nsrc] fp32 row-major  ->  WT_hi/lo [512 rows][K] bf16, rows >= Nsrc zero
__global__ void prep_wT(const float* __restrict__ W, int K, int Nsrc,
                        __nv_bfloat16* __restrict__ hi,
                        __nv_bfloat16* __restrict__ lo) {
    int idx = blockIdx.x * blockDim.x + threadIdx.x;
    if (idx >= 512 * K) return;
    int n = idx / K;
    int k = idx - n * K;
    float v = (n < Nsrc) ? W[(size_t)k * Nsrc + n] : 0.f;
    __nv_bfloat16 h = __float2bfloat16(v);
    hi[idx] = h;
    lo[idx] = __float2bfloat16(v - __bfloat162float(h));
}

// ---------------------------------------------------------------------------
// HMMA fused GEMM (128x256 CTA): C = epi( A[M,K] @ WT^T + bias )
//   GM=0: A direct fp32    GM=1: concat(mesh[src],grid[dst],e0) K=1536
//   GM=2: concat(grid, agg) K=1024
//   ACT: silu   RES: += resid   SCAT: atomicAdd into agg[dst[r]]
// bf16 hi/lo split (3 mma passes), fp32 register accumulators.
// ---------------------------------------------------------------------------
template <int GM, bool ACT, bool RES, bool SCAT>
__global__ void __launch_bounds__(NTHR) gemm_mm(
    const float* __restrict__ A, int lda,
    const __nv_bfloat16* __restrict__ BThi,
    const __nv_bfloat16* __restrict__ BTlo,
    const float* __restrict__ bias,
    const float* __restrict__ resid,
    float* __restrict__ C, int ldc, int Nc,
    const float* __restrict__ gmesh,
    const float* __restrict__ ggrid,
    const float* __restrict__ ge0,
    float* __restrict__ gagg,
    const int* __restrict__ srcIdx,
    const int* __restrict__ dstIdx,
    int M, int K) {
    extern __shared__ char sm[];
    const uint32_t smb = smem_u32(sm);
    const int tid = threadIdx.x;
    const int wid = tid >> 5;
    const int lane = tid & 31;
    const int bm = blockIdx.y * BM;
    const int bn = blockIdx.x * BN;
    const int mbase = (wid >> 2) * 64;   // warp m-block (2)
    const int nbase = (wid & 3) * 64;    // warp n-block (4)

    int* sSrc = (int*)(sm);
    int* sDst = (int*)(sm + 512);
    if (GM == 1) {
        for (int i = tid; i < BM; i += NTHR) {
            int r = bm + i;
            sSrc[i] = (r < M) ? srcIdx[r] : 0;
            sDst[i] = (r < M) ? dstIdx[r] : 0;
        }
        __syncthreads();
    }

    // ---- global A fetch into regs (float4 x4 per thread) ----
    auto ldgA = [&](int c, float4* v) {
        int k0 = c * BK;
#pragma unroll
        for (int it = 0; it < 4; ++it) {
            int idx = it * NTHR + tid;
            int row = idx >> 3;
            int kk = k0 + (idx & 7) * 4;
            int r = bm + row;
            v[it] = make_float4(0.f, 0.f, 0.f, 0.f);
            if (r < M) {
                const float* p;
                if (GM == 0) {
                    p = A + (size_t)r * lda + kk;
                } else if (GM == 1) {
                    if (kk < 512)       p = gmesh + (size_t)sSrc[row] * DDIM + kk;
                    else if (kk < 1024) p = ggrid + (size_t)sDst[row] * DDIM + (kk - 512);
                    else                p = ge0 + (size_t)r * DDIM + (kk - 1024);
                } else {
                    if (kk < 512) p = ggrid + (size_t)r * DDIM + kk;
                    else          p = gagg + (size_t)r * DDIM + (kk - 512);
                }
                v[it] = *(const float4*)p;
            }
        }
    };
    // ---- convert + store A hi/lo into buffer ----
    auto stsA = [&](const float4* v, int buf) {
        char* base = sm + SM_BUFS + buf * SM_BUFSZ;
#pragma unroll
        for (int it = 0; it < 4; ++it) {
            int idx = it * NTHR + tid;
            int row = idx >> 3;
            int cg = idx & 7;
            uint2 H, L;
            split4(v[it], H, L);
            uint32_t off = (uint32_t)(row * SMROW + cg * 8);
            *(uint2*)(base + off) = H;
            *(uint2*)(base + SM_ALO + off) = L;
        }
    };
    // ---- cp.async B hi/lo into buffer (256 rows) ----
    auto cpB = [&](int c, int buf) {
        int k0 = c * BK;
        uint32_t Bb = smb + SM_BUFS + buf * SM_BUFSZ + SM_BHI;
#pragma unroll
        for (int it = 0; it < 4; ++it) {
            int idx = it * NTHR + tid;       // 0..1023
            int row = idx >> 2;              // 0..255
            int ch = idx & 3;
            uint32_t doff = (uint32_t)(row * SMROW + ch * 16);
            size_t g = (size_t)(bn + row) * K + k0 + ch * 8;
            cpasync16(Bb + doff, BThi + g);
            cpasync16(Bb + (SM_BLO - SM_BHI) + doff, BTlo + g);
        }
        cp_commit();
    };

    float acc[4][8][4];
#pragma unroll
    for (int i = 0; i < 4; i++)
#pragma unroll
        for (int j = 0; j < 8; j++)
#pragma unroll
            for (int e = 0; e < 4; e++) acc[i][j][e] = 0.f;

    const int NC = K / BK;
    float4 areg[4];

    // prologue: chunk 0
    ldgA(0, areg);
    cpB(0, 0);
    stsA(areg, 0);

    for (int c = 0; c < NC; ++c) {
        const int buf = c & 1;
        cp_wait_all();
        __syncthreads();
        if (c + 1 < NC) {
            ldgA(c + 1, areg);
            cpB(c + 1, buf ^ 1);
        }
        // ---- compute chunk from buf ----
        const uint32_t Ab = smb + SM_BUFS + buf * SM_BUFSZ;
        const uint32_t Bb = Ab + SM_BHI;
#pragma unroll
        for (int kh = 0; kh < 2; ++kh) {
            uint32_t ahi[4][4], alo[4][4];
#pragma unroll
            for (int i = 0; i < 4; ++i) {
                uint32_t ao = Ab +
                    (uint32_t)((mbase + i * 16 + (lane & 15)) * SMROW +
                               kh * 32 + ((lane >> 4) << 4));
                ldsm4(ahi[i], ao);
                ldsm4(alo[i], ao + SM_ALO);
            }
#pragma unroll
            for (int j2 = 0; j2 < 4; ++j2) {
                uint32_t bh[4], bl[4];
                uint32_t ba = Bb +
                    (uint32_t)((nbase + j2 * 16 + ((lane >> 4) << 3) + (lane & 7)) * SMROW +
                               kh * 32 + ((lane >> 3) & 1) * 16);
                ldsm4(bh, ba);
                ldsm4(bl, ba + (SM_BLO - SM_BHI));
#pragma unroll
                for (int i = 0; i < 4; ++i) {
                    mma_bf16(acc[i][2 * j2],     ahi[i], &bh[0]);
                    mma_bf16(acc[i][2 * j2 + 1], ahi[i], &bh[2]);
                    mma_bf16(acc[i][2 * j2],     alo[i], &bh[0]);
                    mma_bf16(acc[i][2 * j2 + 1], alo[i], &bh[2]);
                    mma_bf16(acc[i][2 * j2],     ahi[i], &bl[0]);
                    mma_bf16(acc[i][2 * j2 + 1], ahi[i], &bl[2]);
                }
            }
        }
        if (c + 1 < NC) stsA(areg, buf ^ 1);
    }

    // ---- epilogue: registers -> global ----
    const int gid = lane >> 2, tig = lane & 3;
#pragma unroll
    for (int i = 0; i < 4; ++i) {
        int r0 = bm + mbase + i * 16 + gid;
        int r1 = r0 + 8;
        int d0 = 0, d1 = 0;
        if (SCAT) {
            d0 = (r0 < M) ? dstIdx[r0] : 0;
            d1 = (r1 < M) ? dstIdx[r1] : 0;
        }
#pragma unroll
        for (int j = 0; j < 8; ++j) {
            int n0 = bn + nbase + j * 8 + tig * 2;
#pragma unroll
            for (int e = 0; e < 4; ++e) {
                int r = (e & 2) ? r1 : r0;
                int dd = (e & 2) ? d1 : d0;
                int n = n0 + (e & 1);
                if (r < M && n < Nc) {
                    float v = acc[i][j][e] + bias[n];
                    if (ACT) v = silu_f(v);
                    if (RES) v += resid[(size_t)r * DDIM + n];
                    if (SCAT)
                        atomicAdd(&gagg[(size_t)dd * DDIM + n], v);
                    else
                        C[(size_t)r * ldc + n] = v;
                }
            }
        }
    }
}

// ---------------------------------------------------------------------------
// Launch (ordered so ncu's "-s 5 -c 1" captures the big stage-3 GEMM)
// ---------------------------------------------------------------------------
extern "C" void kernel_launch(void* const* d_in, const int* in_sizes, int n_in,
                              void* d_out, int out_size) {
    (void)in_sizes; (void)n_in; (void)out_size;

    const float* mesh    = (const float*)d_in[0];
    const float* grid    = (const float*)d_in[1];
    const float* attrs   = (const float*)d_in[2];
    const int*   esrc    = (const int*)d_in[3];
    const int*   edst    = (const int*)d_in[4];
    const float* emb_w0  = (const float*)d_in[5];
    const float* emb_b0  = (const float*)d_in[6];
    const float* emb_w1  = (const float*)d_in[7];
    const float* emb_b1  = (const float*)d_in[8];
    const float* edge_w0 = (const float*)d_in[9];
    const float* edge_b0 = (const float*)d_in[10];
    const float* edge_w1 = (const float*)d_in[11];
    const float* edge_b1 = (const float*)d_in[12];
    const float* node_w0 = (const float*)d_in[13];
    const float* node_b0 = (const float*)d_in[14];
    const float* node_w1 = (const float*)d_in[15];
    const float* node_b1 = (const float*)d_in[16];
    const float* out_w0  = (const float*)d_in[17];
    const float* out_b0  = (const float*)d_in[18];
    const float* out_w1  = (const float*)d_in[19];
    const float* out_b1  = (const float*)d_in[20];
    float* out = (float*)d_out;

    float *pE0, *pH, *pAgg, *pGridNew;
    __nv_bfloat16 *pWThi, *pWTlo;
    cudaGetSymbolAddress((void**)&pE0, g_e0);
    cudaGetSymbolAddress((void**)&pH, g_h);
    cudaGetSymbolAddress((void**)&pAgg, g_agg);
    cudaGetSymbolAddress((void**)&pGridNew, g_gridnew);
    cudaGetSymbolAddress((void**)&pWThi, g_wThi);
    cudaGetSymbolAddress((void**)&pWTlo, g_wTlo);

    cudaFuncSetAttribute(gemm_mm<0, false, false, false>, cudaFuncAttributeMaxDynamicSharedMemorySize, SM_TOTAL);
    cudaFuncSetAttribute(gemm_mm<1, true, false, false>,  cudaFuncAttributeMaxDynamicSharedMemorySize, SM_TOTAL);
    cudaFuncSetAttribute(gemm_mm<0, false, true, true>,   cudaFuncAttributeMaxDynamicSharedMemorySize, SM_TOTAL);
    cudaFuncSetAttribute(gemm_mm<2, true, false, false>,  cudaFuncAttributeMaxDynamicSharedMemorySize, SM_TOTAL);
    cudaFuncSetAttribute(gemm_mm<0, false, true, false>,  cudaFuncAttributeMaxDynamicSharedMemorySize, SM_TOTAL);
    cudaFuncSetAttribute(gemm_mm<0, true, false, false>,  cudaFuncAttributeMaxDynamicSharedMemorySize, SM_TOTAL);

    const int E = NEDGES, G = NGRID;
    dim3 gridE(2, (E + BM - 1) / BM);
    dim3 gridG(2, (G + BM - 1) / BM);

    // #0: edge-embedding layer 1
    {
        size_t tot = (size_t)E * DDIM;
        emb_l1_kernel<<<(unsigned)((tot + 255) / 256), 256>>>(attrs, emb_w0, emb_b0, pH);
    }
    // #1, #2: preps needed by stages 2-3
    prep_wT<<<(512 * 512 + 255) / 256, 256>>>(emb_w1, 512, 512, pWThi + OFF_EMBW1, pWTlo + OFF_EMBW1);
    prep_wT<<<(512 * 1536 + 255) / 256, 256>>>(edge_w0, 1536, 512, pWThi + OFF_EDGEW0, pWTlo + OFF_EDGEW0);
    // #3: e0 = h @ emb_w1 + emb_b1
    gemm_mm<0, false, false, false><<<gridE, NTHR, SM_TOTAL>>>(
        pH, DDIM, pWThi + OFF_EMBW1, pWTlo + OFF_EMBW1, emb_b1, nullptr,
        pE0, DDIM, DDIM, nullptr, nullptr, nullptr, nullptr, nullptr, nullptr, E, DDIM);
    // #4: agg = 0
    {
        size_t n4 = (size_t)G * DDIM / 4;
        zero_kernel<<<(unsigned)((n4 + 255) / 256), 256>>>((float4*)pAgg, n4);
    }
    // #5 (ncu-captured): h = silu( concat(mesh[src],grid[dst],e0) @ edge_w0 + edge_b0 )
    gemm_mm<1, true, false, false><<<gridE, NTHR, SM_TOTAL>>>(
        nullptr, 0, pWThi + OFF_EDGEW0, pWTlo + OFF_EDGEW0, edge_b0, nullptr,
        pH, DDIM, DDIM, mesh, grid, pE0, nullptr, esrc, edst, E, 3 * DDIM);
    // #6: prep edge_w1
    prep_wT<<<(512 * 512 + 255) / 256, 256>>>(edge_w1, 512, 512, pWThi + OFF_EDGEW1, pWTlo + OFF_EDGEW1);
    // #7: agg[dst] += e0 + h @ edge_w1 + edge_b1
    gemm_mm<0, false, true, true><<<gridE, NTHR, SM_TOTAL>>>(
        pH, DDIM, pWThi + OFF_EDGEW1, pWTlo + OFF_EDGEW1, edge_b1, pE0,
        nullptr, DDIM, DDIM, nullptr, nullptr, nullptr, pAgg, nullptr, edst, E, DDIM);
    // #8: prep node_w0
    prep_wT<<<(512 * 1024 + 255) / 256, 256>>>(node_w0, 1024, 512, pWThi + OFF_NODEW0, pWTlo + OFF_NODEW0);
    // #9: h = silu( concat(grid, agg) @ node_w0 + node_b0 )
    gemm_mm<2, true, false, false><<<gridG, NTHR, SM_TOTAL>>>(
        nullptr, 0, pWThi + OFF_NODEW0, pWTlo + OFF_NODEW0, node_b0, nullptr,
        pH, DDIM, DDIM, nullptr, grid, nullptr, pAgg, nullptr, nullptr, G, 2 * DDIM);
    // #10: prep node_w1
    prep_wT<<<(512 * 512 + 255) / 256, 256>>>(node_w1, 512, 512, pWThi + OFF_NODEW1, pWTlo + OFF_NODEW1);
    // #11: grid_new = grid + h @ node_w1 + node_b1
    gemm_mm<0, false, true, false><<<gridG, NTHR, SM_TOTAL>>>(
        pH, DDIM, pWThi + OFF_NODEW1, pWTlo + OFF_NODEW1, node_b1, grid,
        pGridNew, DDIM, DDIM, nullptr, nullptr, nullptr, nullptr, nullptr, nullptr, G, DDIM);
    // #12: prep out_w0
    prep_wT<<<(512 * 512 + 255) / 256, 256>>>(out_w0, 512, 512, pWThi + OFF_OUTW0, pWTlo + OFF_OUTW0);
    // #13: h = silu( grid_new @ out_w0 + out_b0 )
    gemm_mm<0, true, false, false><<<gridG, NTHR, SM_TOTAL>>>(
        pGridNew, DDIM, pWThi + OFF_OUTW0, pWTlo + OFF_OUTW0, out_b0, nullptr,
        pH, DDIM, DDIM, nullptr, nullptr, nullptr, nullptr, nullptr, nullptr, G, DDIM);
    // #14: prep out_w1 (padded 471 -> 512)
    prep_wT<<<(512 * 512 + 255) / 256, 256>>>(out_w1, 512, NOUT, pWThi + OFF_OUTW1, pWTlo + OFF_OUTW1);
    // #15: out = h @ out_w1 + out_b1  (store/bias guard at N=471)
    gemm_mm<0, false, false, false><<<gridG, NTHR, SM_TOTAL>>>(
        pH, DDIM, pWThi + OFF_OUTW1, pWTlo + OFF_OUTW1, out_b1, nullptr,
        out, NOUT, NOUT, nullptr, nullptr, nullptr, nullptr, nullptr, nullptr, G, DDIM);
}

// round 8
// speedup vs baseline: 1.1329x; 1.1329x over previous
#include <cuda_runtime.h>
#include <cuda_bf16.h>
#include <math.h>
#include <stdint.h>
#include <stddef.h>

#define NMESH 10242
#define NGRID 65160
#define NEDGES 195480
#define DDIM 512
#define NOUT 471

// GEMM tiling: CTA 128x256, K-chunk 32 bf16; 16 warps of 64x32
#define BM 128
#define BN 256
#define BK 32
#define GTHR 512

// Smem: [0,512) sSrc, [512,1024) sDst, buffers at 1024
// buffer: Ahi[128][40bf16] (10240B), Alo +10240, Bhi[256][40] @20480, Blo @40960
#define SMROW 80              // padded row stride bytes (32 bf16 = 64B + 16B pad)
#define SM_ALO 10240
#define SM_BHI 20480
#define SM_BLO 40960
#define SM_BUFSZ 61440
#define SM_BUFS 1024
#define SM_TOTAL (SM_BUFS + 2 * SM_BUFSZ)

// ---------------------------------------------------------------------------
// Scratch (device globals — no dynamic allocation allowed)
// ---------------------------------------------------------------------------
__device__ float g_e0[(size_t)NEDGES * DDIM];
__device__ float g_h[(size_t)NEDGES * DDIM];
__device__ float g_agg[(size_t)NGRID * DDIM];
__device__ float g_gridnew[(size_t)NGRID * DDIM];

// Pre-transposed / pre-split weights: [N=512 rows][K] row-major bf16
#define OFF_EMBW1  0u         /* K=512  */
#define OFF_EDGEW0 262144u    /* K=1536 */
#define OFF_EDGEW1 1048576u   /* K=512  */
#define OFF_NODEW0 1310720u   /* K=1024 */
#define OFF_NODEW1 1835008u   /* K=512  */
#define OFF_OUTW0  2097152u   /* K=512  */
#define OFF_OUTW1  2359296u   /* K=512, padded from 471 cols */
#define WT_TOTAL   2621440u
__device__ __nv_bfloat16 g_wThi[WT_TOTAL];
__device__ __nv_bfloat16 g_wTlo[WT_TOTAL];

// ---------------------------------------------------------------------------
// Helpers
// ---------------------------------------------------------------------------
__device__ __forceinline__ uint32_t smem_u32(const void* p) {
    uint32_t a;
    asm("{ .reg .u64 t; cvta.to.shared.u64 t, %1; cvt.u32.u64 %0, t; }"
        : "=r"(a) : "l"(p));
    return a;
}
__device__ __forceinline__ void cpasync16(uint32_t dst, const void* src) {
    asm volatile("cp.async.cg.shared.global [%0], [%1], 16;"
                 :: "r"(dst), "l"(src) : "memory");
}
__device__ __forceinline__ void cp_commit() {
    asm volatile("cp.async.commit_group;" ::: "memory");
}
__device__ __forceinline__ void cp_wait_all() {
    asm volatile("cp.async.wait_group 0;" ::: "memory");
}
__device__ __forceinline__ void ldsm4(uint32_t* r, uint32_t addr) {
    asm volatile("ldmatrix.sync.aligned.m8n8.x4.shared.b16 {%0,%1,%2,%3}, [%4];"
                 : "=r"(r[0]), "=r"(r[1]), "=r"(r[2]), "=r"(r[3]) : "r"(addr));
}
__device__ __forceinline__ void mma_bf16(float* c, const uint32_t* a, const uint32_t* b) {
    asm volatile(
        "mma.sync.aligned.m16n8k16.row.col.f32.bf16.bf16.f32 "
        "{%0,%1,%2,%3}, {%4,%5,%6,%7}, {%8,%9}, {%0,%1,%2,%3};"
        : "+f"(c[0]), "+f"(c[1]), "+f"(c[2]), "+f"(c[3])
        : "r"(a[0]), "r"(a[1]), "r"(a[2]), "r"(a[3]), "r"(b[0]), "r"(b[1]));
}
__device__ __forceinline__ void split4(float4 v, uint2& H, uint2& L) {
    __nv_bfloat16 hx = __float2bfloat16(v.x), hy = __float2bfloat16(v.y);
    __nv_bfloat16 hz = __float2bfloat16(v.z), hw = __float2bfloat16(v.w);
    __nv_bfloat16 lx = __float2bfloat16(v.x - __bfloat162float(hx));
    __nv_bfloat16 ly = __float2bfloat16(v.y - __bfloat162float(hy));
    __nv_bfloat16 lz = __float2bfloat16(v.z - __bfloat162float(hz));
    __nv_bfloat16 lw = __float2bfloat16(v.w - __bfloat162float(hw));
    H.x = (uint32_t)__bfloat16_as_ushort(hx) | ((uint32_t)__bfloat16_as_ushort(hy) << 16);
    H.y = (uint32_t)__bfloat16_as_ushort(hz) | ((uint32_t)__bfloat16_as_ushort(hw) << 16);
    L.x = (uint32_t)__bfloat16_as_ushort(lx) | ((uint32_t)__bfloat16_as_ushort(ly) << 16);
    L.y = (uint32_t)__bfloat16_as_ushort(lz) | ((uint32_t)__bfloat16_as_ushort(lw) << 16);
}
__device__ __forceinline__ float silu_f(float v) {
    return __fdividef(v, 1.0f + __expf(-v));
}

// ---------------------------------------------------------------------------
// Small kernels
// ---------------------------------------------------------------------------
__global__ void emb_l1_kernel(const float* __restrict__ attrs,
                              const float* __restrict__ w0,
                              const float* __restrict__ b0,
                              float* __restrict__ h0) {
    size_t idx = (size_t)blockIdx.x * blockDim.x + threadIdx.x;
    if (idx >= (size_t)NEDGES * DDIM) return;
    int r = (int)(idx >> 9);
    int c = (int)(idx & 511);
    float v = b0[c];
#pragma unroll
    for (int j = 0; j < 4; j++)
        v = fmaf(attrs[r * 4 + j], w0[j * DDIM + c], v);
    h0[idx] = silu_f(v);
}

__global__ void zero_kernel(float4* __restrict__ p, size_t n4) {
    size_t i = (size_t)blockIdx.x * blockDim.x + threadIdx.x;
    if (i < n4) p[i] = make_float4(0.f, 0.f, 0.f, 0.f);
}

// W [K, Nsrc] fp32 row-major  ->  WT_hi/lo [512 rows][K] bf16, rows >= Nsrc zero
__global__ void prep_wT(const float* __restrict__ W, int K, int Nsrc,
                        __nv_bfloat16* __restrict__ hi,
                        __nv_bfloat16* __restrict__ lo) {
    int idx = blockIdx.x * blockDim.x + threadIdx.x;
    if (idx >= 512 * K) return;
    int n = idx / K;
    int k = idx - n * K;
    float v = (n < Nsrc) ? W[(size_t)k * Nsrc + n] : 0.f;
    __nv_bfloat16 h = __float2bfloat16(v);
    hi[idx] = h;
    lo[idx] = __float2bfloat16(v - __bfloat162float(h));
}

// ---------------------------------------------------------------------------
// HMMA fused GEMM (128x256 CTA, 16 warps of 64x32): C = epi( A @ WT^T + bias )
//   GM=0: A direct fp32    GM=1: concat(mesh[src],grid[dst],e0) K=1536
//   GM=2: concat(grid, agg) K=1024
//   ACT: silu   RES: += resid   SCAT: atomicAdd into agg[dst[r]]
// bf16 hi/lo split, 2-pass liveness (pass1: Ahi*(Bhi+Blo); pass2: Alo*Bhi).
// ---------------------------------------------------------------------------
template <int GM, bool ACT, bool RES, bool SCAT>
__global__ void __launch_bounds__(GTHR, 1) gemm_mm(
    const float* __restrict__ A, int lda,
    const __nv_bfloat16* __restrict__ BThi,
    const __nv_bfloat16* __restrict__ BTlo,
    const float* __restrict__ bias,
    const float* __restrict__ resid,
    float* __restrict__ C, int ldc, int Nc,
    const float* __restrict__ gmesh,
    const float* __restrict__ ggrid,
    const float* __restrict__ ge0,
    float* __restrict__ gagg,
    const int* __restrict__ srcIdx,
    const int* __restrict__ dstIdx,
    int M, int K) {
    extern __shared__ char sm[];
    const uint32_t smb = smem_u32(sm);
    const int tid = threadIdx.x;
    const int wid = tid >> 5;
    const int lane = tid & 31;
    const int bm = blockIdx.y * BM;
    const int bn = blockIdx.x * BN;
    const int mbase = (wid >> 3) * 64;   // warp m-block (2)
    const int nbase = (wid & 7) * 32;    // warp n-block (8)

    int* sSrc = (int*)(sm);
    int* sDst = (int*)(sm + 512);
    if (GM == 1) {
        for (int i = tid; i < BM; i += GTHR) {
            int r = bm + i;
            sSrc[i] = (r < M) ? srcIdx[r] : 0;
            sDst[i] = (r < M) ? dstIdx[r] : 0;
        }
        __syncthreads();
    }

    // ---- global A fetch into regs (float4 x2 per thread) ----
    auto ldgA = [&](int c, float4* v) {
        int k0 = c * BK;
#pragma unroll
        for (int it = 0; it < 2; ++it) {
            int idx = it * GTHR + tid;
            int row = idx >> 3;
            int kk = k0 + (idx & 7) * 4;
            int r = bm + row;
            v[it] = make_float4(0.f, 0.f, 0.f, 0.f);
            if (r < M) {
                const float* p;
                if (GM == 0) {
                    p = A + (size_t)r * lda + kk;
                } else if (GM == 1) {
                    if (kk < 512)       p = gmesh + (size_t)sSrc[row] * DDIM + kk;
                    else if (kk < 1024) p = ggrid + (size_t)sDst[row] * DDIM + (kk - 512);
                    else                p = ge0 + (size_t)r * DDIM + (kk - 1024);
                } else {
                    if (kk < 512) p = ggrid + (size_t)r * DDIM + kk;
                    else          p = gagg + (size_t)r * DDIM + (kk - 512);
                }
                v[it] = *(const float4*)p;
            }
        }
    };
    // ---- convert + store A hi/lo into buffer ----
    auto stsA = [&](const float4* v, int buf) {
        char* base = sm + SM_BUFS + buf * SM_BUFSZ;
#pragma unroll
        for (int it = 0; it < 2; ++it) {
            int idx = it * GTHR + tid;
            int row = idx >> 3;
            int cg = idx & 7;
            uint2 H, L;
            split4(v[it], H, L);
            uint32_t off = (uint32_t)(row * SMROW + cg * 8);
            *(uint2*)(base + off) = H;
            *(uint2*)(base + SM_ALO + off) = L;
        }
    };
    // ---- cp.async B hi/lo into buffer (256 rows) ----
    auto cpB = [&](int c, int buf) {
        int k0 = c * BK;
        uint32_t Bb = smb + SM_BUFS + buf * SM_BUFSZ + SM_BHI;
#pragma unroll
        for (int it = 0; it < 2; ++it) {
            int idx = it * GTHR + tid;       // 0..1023
            int row = idx >> 2;              // 0..255
            int ch = idx & 3;
            uint32_t doff = (uint32_t)(row * SMROW + ch * 16);
            size_t g = (size_t)(bn + row) * K + k0 + ch * 8;
            cpasync16(Bb + doff, BThi + g);
            cpasync16(Bb + (SM_BLO - SM_BHI) + doff, BTlo + g);
        }
        cp_commit();
    };

    float acc[4][4][4];
#pragma unroll
    for (int i = 0; i < 4; i++)
#pragma unroll
        for (int j = 0; j < 4; j++)
#pragma unroll
            for (int e = 0; e < 4; e++) acc[i][j][e] = 0.f;

    const int NC = K / BK;
    float4 areg[2];

    // prologue: chunk 0
    ldgA(0, areg);
    cpB(0, 0);
    stsA(areg, 0);

    for (int c = 0; c < NC; ++c) {
        const int buf = c & 1;
        cp_wait_all();
        __syncthreads();
        if (c + 1 < NC) {
            ldgA(c + 1, areg);
            cpB(c + 1, buf ^ 1);
        }
        // ---- compute chunk from buf ----
        const uint32_t Ab = smb + SM_BUFS + buf * SM_BUFSZ;
        const uint32_t Bb = Ab + SM_BHI;
#pragma unroll
        for (int kh = 0; kh < 2; ++kh) {
            const uint32_t acol = (uint32_t)(kh * 32 + ((lane >> 4) << 4));
            const uint32_t bcol = (uint32_t)(kh * 32 + ((lane >> 3) & 1) * 16);
            const uint32_t brow = (uint32_t)(nbase + ((lane >> 4) << 3) + (lane & 7));
            uint32_t af[4][4];
            // ---- pass 1: A-hi x (B-hi + B-lo) ----
#pragma unroll
            for (int i = 0; i < 4; ++i)
                ldsm4(af[i], Ab + (uint32_t)((mbase + i * 16 + (lane & 15)) * SMROW) + acol);
#pragma unroll
            for (int j2 = 0; j2 < 2; ++j2) {
                uint32_t bh[4], bl[4];
                uint32_t ba = Bb + (brow + j2 * 16) * SMROW + bcol;
                ldsm4(bh, ba);
                ldsm4(bl, ba + (SM_BLO - SM_BHI));
#pragma unroll
                for (int i = 0; i < 4; ++i) {
                    mma_bf16(acc[i][2 * j2],     af[i], &bh[0]);
                    mma_bf16(acc[i][2 * j2 + 1], af[i], &bh[2]);
                    mma_bf16(acc[i][2 * j2],     af[i], &bl[0]);
                    mma_bf16(acc[i][2 * j2 + 1], af[i], &bl[2]);
                }
            }
            // ---- pass 2: A-lo x B-hi ----
#pragma unroll
            for (int i = 0; i < 4; ++i)
                ldsm4(af[i], Ab + SM_ALO + (uint32_t)((mbase + i * 16 + (lane & 15)) * SMROW) + acol);
#pragma unroll
            for (int j2 = 0; j2 < 2; ++j2) {
                uint32_t bh[4];
                ldsm4(bh, Bb + (brow + j2 * 16) * SMROW + bcol);
#pragma unroll
                for (int i = 0; i < 4; ++i) {
                    mma_bf16(acc[i][2 * j2],     af[i], &bh[0]);
                    mma_bf16(acc[i][2 * j2 + 1], af[i], &bh[2]);
                }
            }
        }
        if (c + 1 < NC) stsA(areg, buf ^ 1);
    }

    // ---- epilogue: registers -> global ----
    const int gid = lane >> 2, tig = lane & 3;
#pragma unroll
    for (int i = 0; i < 4; ++i) {
        int r0 = bm + mbase + i * 16 + gid;
        int r1 = r0 + 8;
        int d0 = 0, d1 = 0;
        if (SCAT) {
            d0 = (r0 < M) ? dstIdx[r0] : 0;
            d1 = (r1 < M) ? dstIdx[r1] : 0;
        }
#pragma unroll
        for (int j = 0; j < 4; ++j) {
            int n0 = bn + nbase + j * 8 + tig * 2;
#pragma unroll
            for (int e = 0; e < 4; ++e) {
                int r = (e & 2) ? r1 : r0;
                int dd = (e & 2) ? d1 : d0;
                int n = n0 + (e & 1);
                if (r < M && n < Nc) {
                    float v = acc[i][j][e] + bias[n];
                    if (ACT) v = silu_f(v);
                    if (RES) v += resid[(size_t)r * DDIM + n];
                    if (SCAT)
                        atomicAdd(&gagg[(size_t)dd * DDIM + n], v);
                    else
                        C[(size_t)r * ldc + n] = v;
                }
            }
        }
    }
}

// ---------------------------------------------------------------------------
// Launch (ordered so ncu's "-s 5 -c 1" captures the big stage-3 GEMM)
// ---------------------------------------------------------------------------
extern "C" void kernel_launch(void* const* d_in, const int* in_sizes, int n_in,
                              void* d_out, int out_size) {
    (void)in_sizes; (void)n_in; (void)out_size;

    const float* mesh    = (const float*)d_in[0];
    const float* grid    = (const float*)d_in[1];
    const float* attrs   = (const float*)d_in[2];
    const int*   esrc    = (const int*)d_in[3];
    const int*   edst    = (const int*)d_in[4];
    const float* emb_w0  = (const float*)d_in[5];
    const float* emb_b0  = (const float*)d_in[6];
    const float* emb_w1  = (const float*)d_in[7];
    const float* emb_b1  = (const float*)d_in[8];
    const float* edge_w0 = (const float*)d_in[9];
    const float* edge_b0 = (const float*)d_in[10];
    const float* edge_w1 = (const float*)d_in[11];
    const float* edge_b1 = (const float*)d_in[12];
    const float* node_w0 = (const float*)d_in[13];
    const float* node_b0 = (const float*)d_in[14];
    const float* node_w1 = (const float*)d_in[15];
    const float* node_b1 = (const float*)d_in[16];
    const float* out_w0  = (const float*)d_in[17];
    const float* out_b0  = (const float*)d_in[18];
    const float* out_w1  = (const float*)d_in[19];
    const float* out_b1  = (const float*)d_in[20];
    float* out = (float*)d_out;

    float *pE0, *pH, *pAgg, *pGridNew;
    __nv_bfloat16 *pWThi, *pWTlo;
    cudaGetSymbolAddress((void**)&pE0, g_e0);
    cudaGetSymbolAddress((void**)&pH, g_h);
    cudaGetSymbolAddress((void**)&pAgg, g_agg);
    cudaGetSymbolAddress((void**)&pGridNew, g_gridnew);
    cudaGetSymbolAddress((void**)&pWThi, g_wThi);
    cudaGetSymbolAddress((void**)&pWTlo, g_wTlo);

    cudaFuncSetAttribute(gemm_mm<0, false, false, false>, cudaFuncAttributeMaxDynamicSharedMemorySize, SM_TOTAL);
    cudaFuncSetAttribute(gemm_mm<1, true, false, false>,  cudaFuncAttributeMaxDynamicSharedMemorySize, SM_TOTAL);
    cudaFuncSetAttribute(gemm_mm<0, false, true, true>,   cudaFuncAttributeMaxDynamicSharedMemorySize, SM_TOTAL);
    cudaFuncSetAttribute(gemm_mm<2, true, false, false>,  cudaFuncAttributeMaxDynamicSharedMemorySize, SM_TOTAL);
    cudaFuncSetAttribute(gemm_mm<0, false, true, false>,  cudaFuncAttributeMaxDynamicSharedMemorySize, SM_TOTAL);
    cudaFuncSetAttribute(gemm_mm<0, true, false, false>,  cudaFuncAttributeMaxDynamicSharedMemorySize, SM_TOTAL);

    const int E = NEDGES, G = NGRID;
    dim3 gridE(2, (E + BM - 1) / BM);
    dim3 gridG(2, (G + BM - 1) / BM);

    // #0: edge-embedding layer 1
    {
        size_t tot = (size_t)E * DDIM;
        emb_l1_kernel<<<(unsigned)((tot + 255) / 256), 256>>>(attrs, emb_w0, emb_b0, pH);
    }
    // #1, #2: preps needed by stages 2-3
    prep_wT<<<(512 * 512 + 255) / 256, 256>>>(emb_w1, 512, 512, pWThi + OFF_EMBW1, pWTlo + OFF_EMBW1);
    prep_wT<<<(512 * 1536 + 255) / 256, 256>>>(edge_w0, 1536, 512, pWThi + OFF_EDGEW0, pWTlo + OFF_EDGEW0);
    // #3: e0 = h @ emb_w1 + emb_b1
    gemm_mm<0, false, false, false><<<gridE, GTHR, SM_TOTAL>>>(
        pH, DDIM, pWThi + OFF_EMBW1, pWTlo + OFF_EMBW1, emb_b1, nullptr,
        pE0, DDIM, DDIM, nullptr, nullptr, nullptr, nullptr, nullptr, nullptr, E, DDIM);
    // #4: agg = 0
    {
        size_t n4 = (size_t)G * DDIM / 4;
        zero_kernel<<<(unsigned)((n4 + 255) / 256), 256>>>((float4*)pAgg, n4);
    }
    // #5 (ncu-captured): h = silu( concat(mesh[src],grid[dst],e0) @ edge_w0 + edge_b0 )
    gemm_mm<1, true, false, false><<<gridE, GTHR, SM_TOTAL>>>(
        nullptr, 0, pWThi + OFF_EDGEW0, pWTlo + OFF_EDGEW0, edge_b0, nullptr,
        pH, DDIM, DDIM, mesh, grid, pE0, nullptr, esrc, edst, E, 3 * DDIM);
    // #6: prep edge_w1
    prep_wT<<<(512 * 512 + 255) / 256, 256>>>(edge_w1, 512, 512, pWThi + OFF_EDGEW1, pWTlo + OFF_EDGEW1);
    // #7: agg[dst] += e0 + h @ edge_w1 + edge_b1
    gemm_mm<0, false, true, true><<<gridE, GTHR, SM_TOTAL>>>(
        pH, DDIM, pWThi + OFF_EDGEW1, pWTlo + OFF_EDGEW1, edge_b1, pE0,
        nullptr, DDIM, DDIM, nullptr, nullptr, nullptr, pAgg, nullptr, edst, E, DDIM);
    // #8: prep node_w0
    prep_wT<<<(512 * 1024 + 255) / 256, 256>>>(node_w0, 1024, 512, pWThi + OFF_NODEW0, pWTlo + OFF_NODEW0);
    // #9: h = silu( concat(grid, agg) @ node_w0 + node_b0 )
    gemm_mm<2, true, false, false><<<gridG, GTHR, SM_TOTAL>>>(
        nullptr, 0, pWThi + OFF_NODEW0, pWTlo + OFF_NODEW0, node_b0, nullptr,
        pH, DDIM, DDIM, nullptr, grid, nullptr, pAgg, nullptr, nullptr, G, 2 * DDIM);
    // #10: prep node_w1
    prep_wT<<<(512 * 512 + 255) / 256, 256>>>(node_w1, 512, 512, pWThi + OFF_NODEW1, pWTlo + OFF_NODEW1);
    // #11: grid_new = grid + h @ node_w1 + node_b1
    gemm_mm<0, false, true, false><<<gridG, GTHR, SM_TOTAL>>>(
        pH, DDIM, pWThi + OFF_NODEW1, pWTlo + OFF_NODEW1, node_b1, grid,
        pGridNew, DDIM, DDIM, nullptr, nullptr, nullptr, nullptr, nullptr, nullptr, G, DDIM);
    // #12: prep out_w0
    prep_wT<<<(512 * 512 + 255) / 256, 256>>>(out_w0, 512, 512, pWThi + OFF_OUTW0, pWTlo + OFF_OUTW0);
    // #13: h = silu( grid_new @ out_w0 + out_b0 )
    gemm_mm<0, true, false, false><<<gridG, GTHR, SM_TOTAL>>>(
        pGridNew, DDIM, pWThi + OFF_OUTW0, pWTlo + OFF_OUTW0, out_b0, nullptr,
        pH, DDIM, DDIM, nullptr, nullptr, nullptr, nullptr, nullptr, nullptr, G, DDIM);
    // #14: prep out_w1 (padded 471 -> 512)
    prep_wT<<<(512 * 512 + 255) / 256, 256>>>(out_w1, 512, NOUT, pWThi + OFF_OUTW1, pWTlo + OFF_OUTW1);
    // #15: out = h @ out_w1 + out_b1  (store/bias guard at N=471)
    gemm_mm<0, false, false, false><<<gridG, GTHR, SM_TOTAL>>>(
        pH, DDIM, pWThi + OFF_OUTW1, pWTlo + OFF_OUTW1, out_b1, nullptr,
        out, NOUT, NOUT, nullptr, nullptr, nullptr, nullptr, nullptr, nullptr, G, DDIM);
}

// round 10
// speedup vs baseline: 1.2248x; 1.0812x over previous
#include <cuda_runtime.h>
#include <cuda_bf16.h>
#include <math.h>
#include <stdint.h>
#include <stddef.h>

#define NMESH 10242
#define NGRID 65160
#define NEDGES 195480
#define DDIM 512
#define NOUT 471

// GEMM tiling: CTA 128x128, K-chunk 32 bf16; 8 warps of 64x32; 2 CTAs/SM
#define BM 128
#define BN 128
#define BK 32
#define NTHR 256

// Smem: [0,512) sSrc, [512,1024) sDst, buffers at 1024
// buffer: Ahi[128][40bf16] (10240B), Alo +10240, Bhi @20480, Blo @30720
#define SMROW 80              // padded row stride bytes (32 bf16 = 64B + 16B pad)
#define SM_ALO 10240
#define SM_BHI 20480
#define SM_BLO 30720
#define SM_BUFSZ 40960
#define SM_BUFS 1024
#define SM_TOTAL (SM_BUFS + 2 * SM_BUFSZ)

// ---------------------------------------------------------------------------
// Scratch (device globals — no dynamic allocation allowed)
// ---------------------------------------------------------------------------
__device__ float g_e0[(size_t)NEDGES * DDIM];
__device__ float g_h[(size_t)NEDGES * DDIM];
__device__ float g_agg[(size_t)NGRID * DDIM];
__device__ float g_gridnew[(size_t)NGRID * DDIM];

// Pre-transposed / pre-split weights: [N=512 rows][K] row-major bf16
#define OFF_EMBW1  0u         /* K=512  */
#define OFF_EDGEW0 262144u    /* K=1536 */
#define OFF_EDGEW1 1048576u   /* K=512  */
#define OFF_NODEW0 1310720u   /* K=1024 */
#define OFF_NODEW1 1835008u   /* K=512  */
#define OFF_OUTW0  2097152u   /* K=512  */
#define OFF_OUTW1  2359296u   /* K=512, padded from 471 cols */
#define WT_TOTAL   2621440u
__device__ __nv_bfloat16 g_wThi[WT_TOTAL];
__device__ __nv_bfloat16 g_wTlo[WT_TOTAL];

// ---------------------------------------------------------------------------
// Helpers
// ---------------------------------------------------------------------------
__device__ __forceinline__ uint32_t smem_u32(const void* p) {
    uint32_t a;
    asm("{ .reg .u64 t; cvta.to.shared.u64 t, %1; cvt.u32.u64 %0, t; }"
        : "=r"(a) : "l"(p));
    return a;
}
__device__ __forceinline__ void cpasync16(uint32_t dst, const void* src) {
    asm volatile("cp.async.cg.shared.global [%0], [%1], 16;"
                 :: "r"(dst), "l"(src) : "memory");
}
__device__ __forceinline__ void cp_commit() {
    asm volatile("cp.async.commit_group;" ::: "memory");
}
__device__ __forceinline__ void cp_wait_all() {
    asm volatile("cp.async.wait_group 0;" ::: "memory");
}
__device__ __forceinline__ void ldsm4(uint32_t* r, uint32_t addr) {
    asm volatile("ldmatrix.sync.aligned.m8n8.x4.shared.b16 {%0,%1,%2,%3}, [%4];"
                 : "=r"(r[0]), "=r"(r[1]), "=r"(r[2]), "=r"(r[3]) : "r"(addr));
}
__device__ __forceinline__ void mma_bf16(float* c, const uint32_t* a, const uint32_t* b) {
    asm volatile(
        "mma.sync.aligned.m16n8k16.row.col.f32.bf16.bf16.f32 "
        "{%0,%1,%2,%3}, {%4,%5,%6,%7}, {%8,%9}, {%0,%1,%2,%3};"
        : "+f"(c[0]), "+f"(c[1]), "+f"(c[2]), "+f"(c[3])
        : "r"(a[0]), "r"(a[1]), "r"(a[2]), "r"(a[3]), "r"(b[0]), "r"(b[1]));
}
__device__ __forceinline__ void split4(float4 v, uint2& H, uint2& L) {
    __nv_bfloat16 hx = __float2bfloat16(v.x), hy = __float2bfloat16(v.y);
    __nv_bfloat16 hz = __float2bfloat16(v.z), hw = __float2bfloat16(v.w);
    __nv_bfloat16 lx = __float2bfloat16(v.x - __bfloat162float(hx));
    __nv_bfloat16 ly = __float2bfloat16(v.y - __bfloat162float(hy));
    __nv_bfloat16 lz = __float2bfloat16(v.z - __bfloat162float(hz));
    __nv_bfloat16 lw = __float2bfloat16(v.w - __bfloat162float(hw));
    H.x = (uint32_t)__bfloat16_as_ushort(hx) | ((uint32_t)__bfloat16_as_ushort(hy) << 16);
    H.y = (uint32_t)__bfloat16_as_ushort(hz) | ((uint32_t)__bfloat16_as_ushort(hw) << 16);
    L.x = (uint32_t)__bfloat16_as_ushort(lx) | ((uint32_t)__bfloat16_as_ushort(ly) << 16);
    L.y = (uint32_t)__bfloat16_as_ushort(lz) | ((uint32_t)__bfloat16_as_ushort(lw) << 16);
}
__device__ __forceinline__ float silu_f(float v) {
    return __fdividef(v, 1.0f + __expf(-v));
}

// ---------------------------------------------------------------------------
// Small kernels
// ---------------------------------------------------------------------------
__global__ void emb_l1_kernel(const float* __restrict__ attrs,
                              const float* __restrict__ w0,
                              const float* __restrict__ b0,
                              float* __restrict__ h0) {
    size_t idx = (size_t)blockIdx.x * blockDim.x + threadIdx.x;
    if (idx >= (size_t)NEDGES * DDIM) return;
    int r = (int)(idx >> 9);
    int c = (int)(idx & 511);
    float v = b0[c];
#pragma unroll
    for (int j = 0; j < 4; j++)
        v = fmaf(attrs[r * 4 + j], w0[j * DDIM + c], v);
    h0[idx] = silu_f(v);
}

__global__ void zero_kernel(float4* __restrict__ p, size_t n4) {
    size_t i = (size_t)blockIdx.x * blockDim.x + threadIdx.x;
    if (i < n4) p[i] = make_float4(0.f, 0.f, 0.f, 0.f);
}

// W [K, Nsrc] fp32 row-major  ->  WT_hi/lo [512 rows][K] bf16, rows >= Nsrc zero
__global__ void prep_wT(const float* __restrict__ W, int K, int Nsrc,
                        __nv_bfloat16* __restrict__ hi,
                        __nv_bfloat16* __restrict__ lo) {
    int idx = blockIdx.x * blockDim.x + threadIdx.x;
    if (idx >= 512 * K) return;
    int n = idx / K;
    int k = idx - n * K;
    float v = (n < Nsrc) ? W[(size_t)k * Nsrc + n] : 0.f;
    __nv_bfloat16 h = __float2bfloat16(v);
    hi[idx] = h;
    lo[idx] = __float2bfloat16(v - __bfloat162float(h));
}

// ---------------------------------------------------------------------------
// HMMA fused GEMM (128x128 CTA, 8 warps of 64x32, 2 CTAs/SM):
//   C = epi( A @ WT^T + bias )
//   GM=0: A direct fp32    GM=1: concat(mesh[src],grid[dst],e0) K=1536
//   GM=2: concat(grid, agg) K=1024
//   ACT: silu   RES: += resid   SCAT: atomicAdd into agg[dst[r]]
// bf16 hi/lo split, 2-pass liveness, B-hi held across passes.
// ---------------------------------------------------------------------------
template <int GM, bool ACT, bool RES, bool SCAT>
__global__ void __launch_bounds__(NTHR, 2) gemm_mm(
    const float* __restrict__ A, int lda,
    const __nv_bfloat16* __restrict__ BThi,
    const __nv_bfloat16* __restrict__ BTlo,
    const float* __restrict__ bias,
    const float* __restrict__ resid,
    float* __restrict__ C, int ldc, int Nc,
    const float* __restrict__ gmesh,
    const float* __restrict__ ggrid,
    const float* __restrict__ ge0,
    float* __restrict__ gagg,
    const int* __restrict__ srcIdx,
    const int* __restrict__ dstIdx,
    int M, int K) {
    extern __shared__ char sm[];
    const uint32_t smb = smem_u32(sm);
    const int tid = threadIdx.x;
    const int wid = tid >> 5;
    const int lane = tid & 31;
    const int bm = blockIdx.y * BM;
    const int bn = blockIdx.x * BN;
    const int mbase = (wid >> 2) * 64;   // warp m-block (2)
    const int nbase = (wid & 3) * 32;    // warp n-block (4)

    int* sSrc = (int*)(sm);
    int* sDst = (int*)(sm + 512);
    if (GM == 1) {
        for (int i = tid; i < BM; i += NTHR) {
            int r = bm + i;
            sSrc[i] = (r < M) ? srcIdx[r] : 0;
            sDst[i] = (r < M) ? dstIdx[r] : 0;
        }
        __syncthreads();
    }

    // ---- global A fetch into regs (float4 x4 per thread) ----
    auto ldgA = [&](int c, float4* v) {
        int k0 = c * BK;
#pragma unroll
        for (int it = 0; it < 4; ++it) {
            int idx = it * NTHR + tid;
            int row = idx >> 3;
            int kk = k0 + (idx & 7) * 4;
            int r = bm + row;
            v[it] = make_float4(0.f, 0.f, 0.f, 0.f);
            if (r < M) {
                const float* p;
                if (GM == 0) {
                    p = A + (size_t)r * lda + kk;
                } else if (GM == 1) {
                    if (kk < 512)       p = gmesh + (size_t)sSrc[row] * DDIM + kk;
                    else if (kk < 1024) p = ggrid + (size_t)sDst[row] * DDIM + (kk - 512);
                    else                p = ge0 + (size_t)r * DDIM + (kk - 1024);
                } else {
                    if (kk < 512) p = ggrid + (size_t)r * DDIM + kk;
                    else          p = gagg + (size_t)r * DDIM + (kk - 512);
                }
                v[it] = *(const float4*)p;
            }
        }
    };
    // ---- convert + store A hi/lo into buffer ----
    auto stsA = [&](const float4* v, int buf) {
        char* base = sm + SM_BUFS + buf * SM_BUFSZ;
#pragma unroll
        for (int it = 0; it < 4; ++it) {
            int idx = it * NTHR + tid;
            int row = idx >> 3;
            int cg = idx & 7;
            uint2 H, L;
            split4(v[it], H, L);
            uint32_t off = (uint32_t)(row * SMROW + cg * 8);
            *(uint2*)(base + off) = H;
            *(uint2*)(base + SM_ALO + off) = L;
        }
    };
    // ---- cp.async B hi/lo into buffer (128 rows) ----
    auto cpB = [&](int c, int buf) {
        int k0 = c * BK;
        uint32_t Bb = smb + SM_BUFS + buf * SM_BUFSZ + SM_BHI;
#pragma unroll
        for (int it = 0; it < 2; ++it) {
            int idx = it * NTHR + tid;       // 0..511
            int row = idx >> 2;              // 0..127
            int ch = idx & 3;
            uint32_t doff = (uint32_t)(row * SMROW + ch * 16);
            size_t g = (size_t)(bn + row) * K + k0 + ch * 8;
            cpasync16(Bb + doff, BThi + g);
            cpasync16(Bb + (SM_BLO - SM_BHI) + doff, BTlo + g);
        }
        cp_commit();
    };

    float acc[4][4][4];
#pragma unroll
    for (int i = 0; i < 4; i++)
#pragma unroll
        for (int j = 0; j < 4; j++)
#pragma unroll
            for (int e = 0; e < 4; e++) acc[i][j][e] = 0.f;

    const int NC = K / BK;
    float4 areg[4];

    // prologue: chunk 0
    ldgA(0, areg);
    cpB(0, 0);
    stsA(areg, 0);

    for (int c = 0; c < NC; ++c) {
        const int buf = c & 1;
        cp_wait_all();
        __syncthreads();
        if (c + 1 < NC) {
            ldgA(c + 1, areg);
            cpB(c + 1, buf ^ 1);
        }
        // ---- compute chunk from buf ----
        const uint32_t Ab = smb + SM_BUFS + buf * SM_BUFSZ;
        const uint32_t Bb = Ab + SM_BHI;
#pragma unroll
        for (int kh = 0; kh < 2; ++kh) {
            const uint32_t acol = (uint32_t)(kh * 32 + ((lane >> 4) << 4));
            const uint32_t bcol = (uint32_t)(kh * 32 + ((lane >> 3) & 1) * 16);
            const uint32_t brow = (uint32_t)(nbase + ((lane >> 4) << 3) + (lane & 7));
            uint32_t af[4][4], bh[2][4], bl[2][4];
            // B loaded once per kh; bh held across both passes
#pragma unroll
            for (int j2 = 0; j2 < 2; ++j2) {
                uint32_t ba = Bb + (brow + j2 * 16) * SMROW + bcol;
                ldsm4(bh[j2], ba);
                ldsm4(bl[j2], ba + (SM_BLO - SM_BHI));
            }
            // ---- pass 1: A-hi x (B-hi, B-lo) ----
#pragma unroll
            for (int i = 0; i < 4; ++i)
                ldsm4(af[i], Ab + (uint32_t)((mbase + i * 16 + (lane & 15)) * SMROW) + acol);
#pragma unroll
            for (int i = 0; i < 4; ++i)
#pragma unroll
                for (int j2 = 0; j2 < 2; ++j2) {
                    mma_bf16(acc[i][2 * j2],     af[i], &bh[j2][0]);
                    mma_bf16(acc[i][2 * j2 + 1], af[i], &bh[j2][2]);
                    mma_bf16(acc[i][2 * j2],     af[i], &bl[j2][0]);
                    mma_bf16(acc[i][2 * j2 + 1], af[i], &bl[j2][2]);
                }
            // ---- pass 2: A-lo x B-hi (af reused, bh held) ----
#pragma unroll
            for (int i = 0; i < 4; ++i)
                ldsm4(af[i], Ab + SM_ALO + (uint32_t)((mbase + i * 16 + (lane & 15)) * SMROW) + acol);
#pragma unroll
            for (int i = 0; i < 4; ++i)
#pragma unroll
                for (int j2 = 0; j2 < 2; ++j2) {
                    mma_bf16(acc[i][2 * j2],     af[i], &bh[j2][0]);
                    mma_bf16(acc[i][2 * j2 + 1], af[i], &bh[j2][2]);
                }
        }
        if (c + 1 < NC) stsA(areg, buf ^ 1);
    }

    // ---- epilogue: registers -> global ----
    const int gid = lane >> 2, tig = lane & 3;
#pragma unroll
    for (int i = 0; i < 4; ++i) {
        int r0 = bm + mbase + i * 16 + gid;
        int r1 = r0 + 8;
        int d0 = 0, d1 = 0;
        if (SCAT) {
            d0 = (r0 < M) ? dstIdx[r0] : 0;
            d1 = (r1 < M) ? dstIdx[r1] : 0;
        }
#pragma unroll
        for (int j = 0; j < 4; ++j) {
            int n0 = bn + nbase + j * 8 + tig * 2;
#pragma unroll
            for (int e = 0; e < 4; ++e) {
                int r = (e & 2) ? r1 : r0;
                int dd = (e & 2) ? d1 : d0;
                int n = n0 + (e & 1);
                if (r < M && n < Nc) {
                    float v = acc[i][j][e] + bias[n];
                    if (ACT) v = silu_f(v);
                    if (RES) v += resid[(size_t)r * DDIM + n];
                    if (SCAT)
                        atomicAdd(&gagg[(size_t)dd * DDIM + n], v);
                    else
                        C[(size_t)r * ldc + n] = v;
                }
            }
        }
    }
}

// ---------------------------------------------------------------------------
// Launch
// ---------------------------------------------------------------------------
extern "C" void kernel_launch(void* const* d_in, const int* in_sizes, int n_in,
                              void* d_out, int out_size) {
    (void)in_sizes; (void)n_in; (void)out_size;

    const float* mesh    = (const float*)d_in[0];
    const float* grid    = (const float*)d_in[1];
    const float* attrs   = (const float*)d_in[2];
    const int*   esrc    = (const int*)d_in[3];
    const int*   edst    = (const int*)d_in[4];
    const float* emb_w0  = (const float*)d_in[5];
    const float* emb_b0  = (const float*)d_in[6];
    const float* emb_w1  = (const float*)d_in[7];
    const float* emb_b1  = (const float*)d_in[8];
    const float* edge_w0 = (const float*)d_in[9];
    const float* edge_b0 = (const float*)d_in[10];
    const float* edge_w1 = (const float*)d_in[11];
    const float* edge_b1 = (const float*)d_in[12];
    const float* node_w0 = (const float*)d_in[13];
    const float* node_b0 = (const float*)d_in[14];
    const float* node_w1 = (const float*)d_in[15];
    const float* node_b1 = (const float*)d_in[16];
    const float* out_w0  = (const float*)d_in[17];
    const float* out_b0  = (const float*)d_in[18];
    const float* out_w1  = (const float*)d_in[19];
    const float* out_b1  = (const float*)d_in[20];
    float* out = (float*)d_out;

    float *pE0, *pH, *pAgg, *pGridNew;
    __nv_bfloat16 *pWThi, *pWTlo;
    cudaGetSymbolAddress((void**)&pE0, g_e0);
    cudaGetSymbolAddress((void**)&pH, g_h);
    cudaGetSymbolAddress((void**)&pAgg, g_agg);
    cudaGetSymbolAddress((void**)&pGridNew, g_gridnew);
    cudaGetSymbolAddress((void**)&pWThi, g_wThi);
    cudaGetSymbolAddress((void**)&pWTlo, g_wTlo);

    cudaFuncSetAttribute(gemm_mm<0, false, false, false>, cudaFuncAttributeMaxDynamicSharedMemorySize, SM_TOTAL);
    cudaFuncSetAttribute(gemm_mm<1, true, false, false>,  cudaFuncAttributeMaxDynamicSharedMemorySize, SM_TOTAL);
    cudaFuncSetAttribute(gemm_mm<0, false, true, true>,   cudaFuncAttributeMaxDynamicSharedMemorySize, SM_TOTAL);
    cudaFuncSetAttribute(gemm_mm<2, true, false, false>,  cudaFuncAttributeMaxDynamicSharedMemorySize, SM_TOTAL);
    cudaFuncSetAttribute(gemm_mm<0, false, true, false>,  cudaFuncAttributeMaxDynamicSharedMemorySize, SM_TOTAL);
    cudaFuncSetAttribute(gemm_mm<0, true, false, false>,  cudaFuncAttributeMaxDynamicSharedMemorySize, SM_TOTAL);

    const int E = NEDGES, G = NGRID;
    dim3 gridE(4, (E + BM - 1) / BM);
    dim3 gridG(4, (G + BM - 1) / BM);

    // #0: edge-embedding layer 1
    {
        size_t tot = (size_t)E * DDIM;
        emb_l1_kernel<<<(unsigned)((tot + 255) / 256), 256>>>(attrs, emb_w0, emb_b0, pH);
    }
    // #1, #2: preps needed by stages 2-3
    prep_wT<<<(512 * 512 + 255) / 256, 256>>>(emb_w1, 512, 512, pWThi + OFF_EMBW1, pWTlo + OFF_EMBW1);
    prep_wT<<<(512 * 1536 + 255) / 256, 256>>>(edge_w0, 1536, 512, pWThi + OFF_EDGEW0, pWTlo + OFF_EDGEW0);
    // #3: e0 = h @ emb_w1 + emb_b1
    gemm_mm<0, false, false, false><<<gridE, NTHR, SM_TOTAL>>>(
        pH, DDIM, pWThi + OFF_EMBW1, pWTlo + OFF_EMBW1, emb_b1, nullptr,
        pE0, DDIM, DDIM, nullptr, nullptr, nullptr, nullptr, nullptr, nullptr, E, DDIM);
    // #4: agg = 0
    {
        size_t n4 = (size_t)G * DDIM / 4;
        zero_kernel<<<(unsigned)((n4 + 255) / 256), 256>>>((float4*)pAgg, n4);
    }
    // #5: h = silu( concat(mesh[src],grid[dst],e0) @ edge_w0 + edge_b0 )
    gemm_mm<1, true, false, false><<<gridE, NTHR, SM_TOTAL>>>(
        nullptr, 0, pWThi + OFF_EDGEW0, pWTlo + OFF_EDGEW0, edge_b0, nullptr,
        pH, DDIM, DDIM, mesh, grid, pE0, nullptr, esrc, edst, E, 3 * DDIM);
    // #6: prep edge_w1
    prep_wT<<<(512 * 512 + 255) / 256, 256>>>(edge_w1, 512, 512, pWThi + OFF_EDGEW1, pWTlo + OFF_EDGEW1);
    // #7: agg[dst] += e0 + h @ edge_w1 + edge_b1
    gemm_mm<0, false, true, true><<<gridE, NTHR, SM_TOTAL>>>(
        pH, DDIM, pWThi + OFF_EDGEW1, pWTlo + OFF_EDGEW1, edge_b1, pE0,
        nullptr, DDIM, DDIM, nullptr, nullptr, nullptr, pAgg, nullptr, edst, E, DDIM);
    // #8: prep node_w0
    prep_wT<<<(512 * 1024 + 255) / 256, 256>>>(node_w0, 1024, 512, pWThi + OFF_NODEW0, pWTlo + OFF_NODEW0);
    // #9: h = silu( concat(grid, agg) @ node_w0 + node_b0 )
    gemm_mm<2, true, false, false><<<gridG, NTHR, SM_TOTAL>>>(
        nullptr, 0, pWThi + OFF_NODEW0, pWTlo + OFF_NODEW0, node_b0, nullptr,
        pH, DDIM, DDIM, nullptr, grid, nullptr, pAgg, nullptr, nullptr, G, 2 * DDIM);
    // #10: prep node_w1
    prep_wT<<<(512 * 512 + 255) / 256, 256>>>(node_w1, 512, 512, pWThi + OFF_NODEW1, pWTlo + OFF_NODEW1);
    // #11: grid_new = grid + h @ node_w1 + node_b1
    gemm_mm<0, false, true, false><<<gridG, NTHR, SM_TOTAL>>>(
        pH, DDIM, pWThi + OFF_NODEW1, pWTlo + OFF_NODEW1, node_b1, grid,
        pGridNew, DDIM, DDIM, nullptr, nullptr, nullptr, nullptr, nullptr, nullptr, G, DDIM);
    // #12: prep out_w0
    prep_wT<<<(512 * 512 + 255) / 256, 256>>>(out_w0, 512, 512, pWThi + OFF_OUTW0, pWTlo + OFF_OUTW0);
    // #13: h = silu( grid_new @ out_w0 + out_b0 )
    gemm_mm<0, true, false, false><<<gridG, NTHR, SM_TOTAL>>>(
        pGridNew, DDIM, pWThi + OFF_OUTW0, pWTlo + OFF_OUTW0, out_b0, nullptr,
        pH, DDIM, DDIM, nullptr, nullptr, nullptr, nullptr, nullptr, nullptr, G, DDIM);
    // #14: prep out_w1 (padded 471 -> 512)
    prep_wT<<<(512 * 512 + 255) / 256, 256>>>(out_w1, 512, NOUT, pWThi + OFF_OUTW1, pWTlo + OFF_OUTW1);
    // #15: out = h @ out_w1 + out_b1  (store/bias guard at N=471)
    gemm_mm<0, false, false, false><<<gridG, NTHR, SM_TOTAL>>>(
        pH, DDIM, pWThi + OFF_OUTW1, pWTlo + OFF_OUTW1, out_b1, nullptr,
        out, NOUT, NOUT, nullptr, nullptr, nullptr, nullptr, nullptr, nullptr, G, DDIM);
}

// round 12
// speedup vs baseline: 1.4483x; 1.1825x over previous
#include <cuda_runtime.h>
#include <cuda_bf16.h>
#include <math.h>
#include <stdint.h>
#include <stddef.h>

#define NMESH 10242
#define NGRID 65160
#define NEDGES 195480
#define DDIM 512
#define NOUT 471

// GEMM tiling: CTA 128x128, K-chunk 32 bf16; 8 warps of 64x32; 2 CTAs/SM
#define BM 128
#define BN 128
#define BK 32
#define NTHR 256

#define SMROW 80
#define SM_ALO 10240
#define SM_BHI 20480
#define SM_BLO 30720
#define SM_BUFSZ 40960
#define SM_BUFS 1024
#define SM_TOTAL (SM_BUFS + 2 * SM_BUFSZ)

// ---------------------------------------------------------------------------
// Scratch (device globals — no dynamic allocation allowed)
// ---------------------------------------------------------------------------
__device__ float g_e0[(size_t)NEDGES * DDIM];
__device__ float g_h[(size_t)NEDGES * DDIM];
__device__ float g_agg[(size_t)NGRID * DDIM];
__device__ float g_gridnew[(size_t)NGRID * DDIM];
__device__ float g_um[(size_t)NMESH * DDIM];   // mesh @ W_m
__device__ float g_ug[(size_t)NGRID * DDIM];   // grid @ W_g
__device__ float g_zbias[DDIM];                // zero bias

// Pre-transposed / pre-split weights: [N=512 rows][K] row-major bf16
#define OFF_EMBW1  0u         /* K=512 */
#define OFF_WM     262144u    /* K=512 (edge_w0 rows 0-511)     */
#define OFF_WG     524288u    /* K=512 (edge_w0 rows 512-1023)  */
#define OFF_WE     786432u    /* K=512 (edge_w0 rows 1024-1535) */
#define OFF_EDGEW1 1048576u   /* K=512  */
#define OFF_NODEW0 1310720u   /* K=1024 */
#define OFF_NODEW1 1835008u   /* K=512  */
#define OFF_OUTW0  2097152u   /* K=512  */
#define OFF_OUTW1  2359296u   /* K=512, padded from 471 cols */
#define WT_TOTAL   2621440u
__device__ __nv_bfloat16 g_wThi[WT_TOTAL];
__device__ __nv_bfloat16 g_wTlo[WT_TOTAL];

// ---------------------------------------------------------------------------
// Helpers
// ---------------------------------------------------------------------------
__device__ __forceinline__ uint32_t smem_u32(const void* p) {
    uint32_t a;
    asm("{ .reg .u64 t; cvta.to.shared.u64 t, %1; cvt.u32.u64 %0, t; }"
        : "=r"(a) : "l"(p));
    return a;
}
__device__ __forceinline__ void cpasync16(uint32_t dst, const void* src) {
    asm volatile("cp.async.cg.shared.global [%0], [%1], 16;"
                 :: "r"(dst), "l"(src) : "memory");
}
__device__ __forceinline__ void cp_commit() {
    asm volatile("cp.async.commit_group;" ::: "memory");
}
__device__ __forceinline__ void cp_wait_all() {
    asm volatile("cp.async.wait_group 0;" ::: "memory");
}
__device__ __forceinline__ void ldsm4(uint32_t* r, uint32_t addr) {
    asm volatile("ldmatrix.sync.aligned.m8n8.x4.shared.b16 {%0,%1,%2,%3}, [%4];"
                 : "=r"(r[0]), "=r"(r[1]), "=r"(r[2]), "=r"(r[3]) : "r"(addr));
}
__device__ __forceinline__ void mma_bf16(float* c, const uint32_t* a, const uint32_t* b) {
    asm volatile(
        "mma.sync.aligned.m16n8k16.row.col.f32.bf16.bf16.f32 "
        "{%0,%1,%2,%3}, {%4,%5,%6,%7}, {%8,%9}, {%0,%1,%2,%3};"
        : "+f"(c[0]), "+f"(c[1]), "+f"(c[2]), "+f"(c[3])
        : "r"(a[0]), "r"(a[1]), "r"(a[2]), "r"(a[3]), "r"(b[0]), "r"(b[1]));
}
__device__ __forceinline__ void split4(float4 v, uint2& H, uint2& L) {
    __nv_bfloat16 hx = __float2bfloat16(v.x), hy = __float2bfloat16(v.y);
    __nv_bfloat16 hz = __float2bfloat16(v.z), hw = __float2bfloat16(v.w);
    __nv_bfloat16 lx = __float2bfloat16(v.x - __bfloat162float(hx));
    __nv_bfloat16 ly = __float2bfloat16(v.y - __bfloat162float(hy));
    __nv_bfloat16 lz = __float2bfloat16(v.z - __bfloat162float(hz));
    __nv_bfloat16 lw = __float2bfloat16(v.w - __bfloat162float(hw));
    H.x = (uint32_t)__bfloat16_as_ushort(hx) | ((uint32_t)__bfloat16_as_ushort(hy) << 16);
    H.y = (uint32_t)__bfloat16_as_ushort(hz) | ((uint32_t)__bfloat16_as_ushort(hw) << 16);
    L.x = (uint32_t)__bfloat16_as_ushort(lx) | ((uint32_t)__bfloat16_as_ushort(ly) << 16);
    L.y = (uint32_t)__bfloat16_as_ushort(lz) | ((uint32_t)__bfloat16_as_ushort(lw) << 16);
}
__device__ __forceinline__ float silu_f(float v) {
    return __fdividef(v, 1.0f + __expf(-v));
}

// ---------------------------------------------------------------------------
// Small kernels
// ---------------------------------------------------------------------------
__global__ void emb_l1_kernel(const float* __restrict__ attrs,
                              const float* __restrict__ w0,
                              const float* __restrict__ b0,
                              float* __restrict__ h0) {
    size_t idx = (size_t)blockIdx.x * blockDim.x + threadIdx.x;
    if (idx >= (size_t)NEDGES * DDIM) return;
    int r = (int)(idx >> 9);
    int c = (int)(idx & 511);
    float v = b0[c];
#pragma unroll
    for (int j = 0; j < 4; j++)
        v = fmaf(attrs[r * 4 + j], w0[j * DDIM + c], v);
    h0[idx] = silu_f(v);
}

__global__ void zero_kernel(float4* __restrict__ p, size_t n4) {
    size_t i = (size_t)blockIdx.x * blockDim.x + threadIdx.x;
    if (i < n4) p[i] = make_float4(0.f, 0.f, 0.f, 0.f);
}

// W [K, Nsrc] fp32 row-major  ->  WT_hi/lo [512 rows][K] bf16, rows >= Nsrc zero
__global__ void prep_wT(const float* __restrict__ W, int K, int Nsrc,
                        __nv_bfloat16* __restrict__ hi,
                        __nv_bfloat16* __restrict__ lo) {
    int idx = blockIdx.x * blockDim.x + threadIdx.x;
    if (idx >= 512 * K) return;
    int n = idx / K;
    int k = idx - n * K;
    float v = (n < Nsrc) ? W[(size_t)k * Nsrc + n] : 0.f;
    __nv_bfloat16 h = __float2bfloat16(v);
    hi[idx] = h;
    lo[idx] = __float2bfloat16(v - __bfloat162float(h));
}

// ---------------------------------------------------------------------------
// HMMA fused GEMM (128x128 CTA, 8 warps of 64x32, 2 CTAs/SM):
//   C = epi( A @ WT^T + bias )
//   GM=0: A direct fp32    GM=2: concat(grid, agg) K=1024
//   ACT: silu   RES: += resid   SCAT: atomicAdd into agg[dst[r]]
//   GADD: += gmesh[src[r]][n] + ggrid[dst[r]][n]  (pre-activation gather-add)
// bf16 hi/lo split, 2-pass liveness, B-hi held across passes.
// ---------------------------------------------------------------------------
template <int GM, bool ACT, bool RES, bool SCAT, bool GADD>
__global__ void __launch_bounds__(NTHR, 2) gemm_mm(
    const float* __restrict__ A, int lda,
    const __nv_bfloat16* __restrict__ BThi,
    const __nv_bfloat16* __restrict__ BTlo,
    const float* __restrict__ bias,
    const float* __restrict__ resid,
    float* __restrict__ C, int ldc, int Nc,
    const float* __restrict__ gmesh,
    const float* __restrict__ ggrid,
    const float* __restrict__ ge0,
    float* __restrict__ gagg,
    const int* __restrict__ srcIdx,
    const int* __restrict__ dstIdx,
    int M, int K) {
    extern __shared__ char sm[];
    const uint32_t smb = smem_u32(sm);
    const int tid = threadIdx.x;
    const int wid = tid >> 5;
    const int lane = tid & 31;
    const int bm = blockIdx.y * BM;
    const int bn = blockIdx.x * BN;
    const int mbase = (wid >> 2) * 64;   // warp m-block (2)
    const int nbase = (wid & 3) * 32;    // warp n-block (4)

    int* sSrc = (int*)(sm);
    int* sDst = (int*)(sm + 512);
    if (GADD) {
        for (int i = tid; i < BM; i += NTHR) {
            int r = bm + i;
            sSrc[i] = (r < M) ? srcIdx[r] : 0;
            sDst[i] = (r < M) ? dstIdx[r] : 0;
        }
        __syncthreads();
    }

    // ---- global A fetch into regs (float4 x4 per thread) ----
    auto ldgA = [&](int c, float4* v) {
        int k0 = c * BK;
#pragma unroll
        for (int it = 0; it < 4; ++it) {
            int idx = it * NTHR + tid;
            int row = idx >> 3;
            int kk = k0 + (idx & 7) * 4;
            int r = bm + row;
            v[it] = make_float4(0.f, 0.f, 0.f, 0.f);
            if (r < M) {
                const float* p;
                if (GM == 0) {
                    p = A + (size_t)r * lda + kk;
                } else {
                    if (kk < 512) p = ggrid + (size_t)r * DDIM + kk;
                    else          p = gagg + (size_t)r * DDIM + (kk - 512);
                }
                v[it] = *(const float4*)p;
            }
        }
    };
    // ---- convert + store A hi/lo into buffer ----
    auto stsA = [&](const float4* v, int buf) {
        char* base = sm + SM_BUFS + buf * SM_BUFSZ;
#pragma unroll
        for (int it = 0; it < 4; ++it) {
            int idx = it * NTHR + tid;
            int row = idx >> 3;
            int cg = idx & 7;
            uint2 H, L;
            split4(v[it], H, L);
            uint32_t off = (uint32_t)(row * SMROW + cg * 8);
            *(uint2*)(base + off) = H;
            *(uint2*)(base + SM_ALO + off) = L;
        }
    };
    // ---- cp.async B hi/lo into buffer (128 rows) ----
    auto cpB = [&](int c, int buf) {
        int k0 = c * BK;
        uint32_t Bb = smb + SM_BUFS + buf * SM_BUFSZ + SM_BHI;
#pragma unroll
        for (int it = 0; it < 2; ++it) {
            int idx = it * NTHR + tid;       // 0..511
            int row = idx >> 2;              // 0..127
            int ch = idx & 3;
            uint32_t doff = (uint32_t)(row * SMROW + ch * 16);
            size_t g = (size_t)(bn + row) * K + k0 + ch * 8;
            cpasync16(Bb + doff, BThi + g);
            cpasync16(Bb + (SM_BLO - SM_BHI) + doff, BTlo + g);
        }
        cp_commit();
    };

    float acc[4][4][4];
#pragma unroll
    for (int i = 0; i < 4; i++)
#pragma unroll
        for (int j = 0; j < 4; j++)
#pragma unroll
            for (int e = 0; e < 4; e++) acc[i][j][e] = 0.f;

    const int NC = K / BK;
    float4 areg[4];

    // prologue: chunk 0
    ldgA(0, areg);
    cpB(0, 0);
    stsA(areg, 0);

    for (int c = 0; c < NC; ++c) {
        const int buf = c & 1;
        cp_wait_all();
        __syncthreads();
        if (c + 1 < NC) {
            ldgA(c + 1, areg);
            cpB(c + 1, buf ^ 1);
        }
        // ---- compute chunk from buf ----
        const uint32_t Ab = smb + SM_BUFS + buf * SM_BUFSZ;
        const uint32_t Bb = Ab + SM_BHI;
#pragma unroll
        for (int kh = 0; kh < 2; ++kh) {
            const uint32_t acol = (uint32_t)(kh * 32 + ((lane >> 4) << 4));
            const uint32_t bcol = (uint32_t)(kh * 32 + ((lane >> 3) & 1) * 16);
            const uint32_t brow = (uint32_t)(nbase + ((lane >> 4) << 3) + (lane & 7));
            uint32_t af[4][4], bh[2][4], bl[2][4];
#pragma unroll
            for (int j2 = 0; j2 < 2; ++j2) {
                uint32_t ba = Bb + (brow + j2 * 16) * SMROW + bcol;
                ldsm4(bh[j2], ba);
                ldsm4(bl[j2], ba + (SM_BLO - SM_BHI));
            }
            // ---- pass 1: A-hi x (B-hi, B-lo) ----
#pragma unroll
            for (int i = 0; i < 4; ++i)
                ldsm4(af[i], Ab + (uint32_t)((mbase + i * 16 + (lane & 15)) * SMROW) + acol);
#pragma unroll
            for (int i = 0; i < 4; ++i)
#pragma unroll
                for (int j2 = 0; j2 < 2; ++j2) {
                    mma_bf16(acc[i][2 * j2],     af[i], &bh[j2][0]);
                    mma_bf16(acc[i][2 * j2 + 1], af[i], &bh[j2][2]);
                    mma_bf16(acc[i][2 * j2],     af[i], &bl[j2][0]);
                    mma_bf16(acc[i][2 * j2 + 1], af[i], &bl[j2][2]);
                }
            // ---- pass 2: A-lo x B-hi (af reused, bh held) ----
#pragma unroll
            for (int i = 0; i < 4; ++i)
                ldsm4(af[i], Ab + SM_ALO + (uint32_t)((mbase + i * 16 + (lane & 15)) * SMROW) + acol);
#pragma unroll
            for (int i = 0; i < 4; ++i)
#pragma unroll
                for (int j2 = 0; j2 < 2; ++j2) {
                    mma_bf16(acc[i][2 * j2],     af[i], &bh[j2][0]);
                    mma_bf16(acc[i][2 * j2 + 1], af[i], &bh[j2][2]);
                }
        }
        if (c + 1 < NC) stsA(areg, buf ^ 1);
    }

    // ---- epilogue: registers -> global ----
    const int gid = lane >> 2, tig = lane & 3;
#pragma unroll
    for (int i = 0; i < 4; ++i) {
        int l0 = mbase + i * 16 + gid;
        int l1 = l0 + 8;
        int r0 = bm + l0;
        int r1 = bm + l1;
        int d0 = 0, d1 = 0;
        if (SCAT) {
            d0 = (r0 < M) ? dstIdx[r0] : 0;
            d1 = (r1 < M) ? dstIdx[r1] : 0;
        }
#pragma unroll
        for (int j = 0; j < 4; ++j) {
            int n0 = bn + nbase + j * 8 + tig * 2;
#pragma unroll
            for (int e = 0; e < 4; ++e) {
                int r = (e & 2) ? r1 : r0;
                int lr = (e & 2) ? l1 : l0;
                int dd = (e & 2) ? d1 : d0;
                int n = n0 + (e & 1);
                if (r < M && n < Nc) {
                    float v = acc[i][j][e] + bias[n];
                    if (GADD)
                        v += gmesh[(size_t)sSrc[lr] * DDIM + n] +
                             ggrid[(size_t)sDst[lr] * DDIM + n];
                    if (ACT) v = silu_f(v);
                    if (RES) v += resid[(size_t)r * DDIM + n];
                    if (SCAT)
                        atomicAdd(&gagg[(size_t)dd * DDIM + n], v);
                    else
                        C[(size_t)r * ldc + n] = v;
                }
            }
        }
    }
}

// ---------------------------------------------------------------------------
// Launch
// ---------------------------------------------------------------------------
extern "C" void kernel_launch(void* const* d_in, const int* in_sizes, int n_in,
                              void* d_out, int out_size) {
    (void)in_sizes; (void)n_in; (void)out_size;

    const float* mesh    = (const float*)d_in[0];
    const float* grid    = (const float*)d_in[1];
    const float* attrs   = (const float*)d_in[2];
    const int*   esrc    = (const int*)d_in[3];
    const int*   edst    = (const int*)d_in[4];
    const float* emb_w0  = (const float*)d_in[5];
    const float* emb_b0  = (const float*)d_in[6];
    const float* emb_w1  = (const float*)d_in[7];
    const float* emb_b1  = (const float*)d_in[8];
    const float* edge_w0 = (const float*)d_in[9];
    const float* edge_b0 = (const float*)d_in[10];
    const float* edge_w1 = (const float*)d_in[11];
    const float* edge_b1 = (const float*)d_in[12];
    const float* node_w0 = (const float*)d_in[13];
    const float* node_b0 = (const float*)d_in[14];
    const float* node_w1 = (const float*)d_in[15];
    const float* node_b1 = (const float*)d_in[16];
    const float* out_w0  = (const float*)d_in[17];
    const float* out_b0  = (const float*)d_in[18];
    const float* out_w1  = (const float*)d_in[19];
    const float* out_b1  = (const float*)d_in[20];
    float* out = (float*)d_out;

    float *pE0, *pH, *pAgg, *pGridNew, *pUm, *pUg, *pZb;
    __nv_bfloat16 *pWThi, *pWTlo;
    cudaGetSymbolAddress((void**)&pE0, g_e0);
    cudaGetSymbolAddress((void**)&pH, g_h);
    cudaGetSymbolAddress((void**)&pAgg, g_agg);
    cudaGetSymbolAddress((void**)&pGridNew, g_gridnew);
    cudaGetSymbolAddress((void**)&pUm, g_um);
    cudaGetSymbolAddress((void**)&pUg, g_ug);
    cudaGetSymbolAddress((void**)&pZb, g_zbias);
    cudaGetSymbolAddress((void**)&pWThi, g_wThi);
    cudaGetSymbolAddress((void**)&pWTlo, g_wTlo);

    cudaFuncSetAttribute(gemm_mm<0, false, false, false, false>, cudaFuncAttributeMaxDynamicSharedMemorySize, SM_TOTAL);
    cudaFuncSetAttribute(gemm_mm<0, true,  false, false, true>,  cudaFuncAttributeMaxDynamicSharedMemorySize, SM_TOTAL);
    cudaFuncSetAttribute(gemm_mm<0, false, true,  true,  false>, cudaFuncAttributeMaxDynamicSharedMemorySize, SM_TOTAL);
    cudaFuncSetAttribute(gemm_mm<2, true,  false, false, false>, cudaFuncAttributeMaxDynamicSharedMemorySize, SM_TOTAL);
    cudaFuncSetAttribute(gemm_mm<0, false, true,  false, false>, cudaFuncAttributeMaxDynamicSharedMemorySize, SM_TOTAL);
    cudaFuncSetAttribute(gemm_mm<0, true,  false, false, false>, cudaFuncAttributeMaxDynamicSharedMemorySize, SM_TOTAL);

    const int E = NEDGES, G = NGRID;
    dim3 gridE(4, (E + BM - 1) / BM);
    dim3 gridG(4, (G + BM - 1) / BM);
    dim3 gridM(4, (NMESH + BM - 1) / BM);

    // #0: edge-embedding layer 1: h = silu(attrs @ emb_w0 + emb_b0)
    {
        size_t tot = (size_t)E * DDIM;
        emb_l1_kernel<<<(unsigned)((tot + 255) / 256), 256>>>(attrs, emb_w0, emb_b0, pH);
    }
    // #1: zero bias vector (for U_m / U_g GEMMs)
    zero_kernel<<<1, 128>>>((float4*)pZb, DDIM / 4);
    // #2-#4: preps (emb_w1, W_e, W_m)
    prep_wT<<<(512 * 512 + 255) / 256, 256>>>(emb_w1, 512, 512, pWThi + OFF_EMBW1, pWTlo + OFF_EMBW1);
    prep_wT<<<(512 * 512 + 255) / 256, 256>>>(edge_w0 + (size_t)1024 * 512, 512, 512, pWThi + OFF_WE, pWTlo + OFF_WE);
    prep_wT<<<(512 * 512 + 255) / 256, 256>>>(edge_w0, 512, 512, pWThi + OFF_WM, pWTlo + OFF_WM);
    // #5 (ncu-captured): e0 = h @ emb_w1 + emb_b1   (E x 512 x 512)
    gemm_mm<0, false, false, false, false><<<gridE, NTHR, SM_TOTAL>>>(
        pH, DDIM, pWThi + OFF_EMBW1, pWTlo + OFF_EMBW1, emb_b1, nullptr,
        pE0, DDIM, DDIM, nullptr, nullptr, nullptr, nullptr, nullptr, nullptr, E, DDIM);
    // #6: prep W_g
    prep_wT<<<(512 * 512 + 255) / 256, 256>>>(edge_w0 + (size_t)512 * 512, 512, 512, pWThi + OFF_WG, pWTlo + OFF_WG);
    // #7: U_m = mesh @ W_m   (10242 rows)
    gemm_mm<0, false, false, false, false><<<gridM, NTHR, SM_TOTAL>>>(
        mesh, DDIM, pWThi + OFF_WM, pWTlo + OFF_WM, pZb, nullptr,
        pUm, DDIM, DDIM, nullptr, nullptr, nullptr, nullptr, nullptr, nullptr, NMESH, DDIM);
    // #8: U_g = grid @ W_g   (65160 rows)
    gemm_mm<0, false, false, false, false><<<gridG, NTHR, SM_TOTAL>>>(
        grid, DDIM, pWThi + OFF_WG, pWTlo + OFF_WG, pZb, nullptr,
        pUg, DDIM, DDIM, nullptr, nullptr, nullptr, nullptr, nullptr, nullptr, G, DDIM);
    // #9: agg = 0
    {
        size_t n4 = (size_t)G * DDIM / 4;
        zero_kernel<<<(unsigned)((n4 + 255) / 256), 256>>>((float4*)pAgg, n4);
    }
    // #10: h = silu( e0 @ W_e + edge_b0 + U_m[src] + U_g[dst] )   (K=512!)
    gemm_mm<0, true, false, false, true><<<gridE, NTHR, SM_TOTAL>>>(
        pE0, DDIM, pWThi + OFF_WE, pWTlo + OFF_WE, edge_b0, nullptr,
        pH, DDIM, DDIM, pUm, pUg, nullptr, nullptr, esrc, edst, E, DDIM);
    // #11: prep edge_w1
    prep_wT<<<(512 * 512 + 255) / 256, 256>>>(edge_w1, 512, 512, pWThi + OFF_EDGEW1, pWTlo + OFF_EDGEW1);
    // #12: agg[dst] += e0 + h @ edge_w1 + edge_b1
    gemm_mm<0, false, true, true, false><<<gridE, NTHR, SM_TOTAL>>>(
        pH, DDIM, pWThi + OFF_EDGEW1, pWTlo + OFF_EDGEW1, edge_b1, pE0,
        nullptr, DDIM, DDIM, nullptr, nullptr, nullptr, pAgg, nullptr, edst, E, DDIM);
    // #13: prep node_w0
    prep_wT<<<(512 * 1024 + 255) / 256, 256>>>(node_w0, 1024, 512, pWThi + OFF_NODEW0, pWTlo + OFF_NODEW0);
    // #14: h = silu( concat(grid, agg) @ node_w0 + node_b0 )
    gemm_mm<2, true, false, false, false><<<gridG, NTHR, SM_TOTAL>>>(
        nullptr, 0, pWThi + OFF_NODEW0, pWTlo + OFF_NODEW0, node_b0, nullptr,
        pH, DDIM, DDIM, nullptr, grid, nullptr, pAgg, nullptr, nullptr, G, 2 * DDIM);
    // #15: prep node_w1
    prep_wT<<<(512 * 512 + 255) / 256, 256>>>(node_w1, 512, 512, pWThi + OFF_NODEW1, pWTlo + OFF_NODEW1);
    // #16: grid_new = grid + h @ node_w1 + node_b1
    gemm_mm<0, false, true, false, false><<<gridG, NTHR, SM_TOTAL>>>(
        pH, DDIM, pWThi + OFF_NODEW1, pWTlo + OFF_NODEW1, node_b1, grid,
        pGridNew, DDIM, DDIM, nullptr, nullptr, nullptr, nullptr, nullptr, nullptr, G, DDIM);
    // #17: prep out_w0
    prep_wT<<<(512 * 512 + 255) / 256, 256>>>(out_w0, 512, 512, pWThi + OFF_OUTW0, pWTlo + OFF_OUTW0);
    // #18: h = silu( grid_new @ out_w0 + out_b0 )
    gemm_mm<0, true, false, false, false><<<gridG, NTHR, SM_TOTAL>>>(
        pGridNew, DDIM, pWThi + OFF_OUTW0, pWTlo + OFF_OUTW0, out_b0, nullptr,
        pH, DDIM, DDIM, nullptr, nullptr, nullptr, nullptr, nullptr, nullptr, G, DDIM);
    // #19: prep out_w1 (padded 471 -> 512)
    prep_wT<<<(512 * 512 + 255) / 256, 256>>>(out_w1, 512, NOUT, pWThi + OFF_OUTW1, pWTlo + OFF_OUTW1);
    // #20: out = h @ out_w1 + out_b1  (store/bias guard at N=471)
    gemm_mm<0, false, false, false, false><<<gridG, NTHR, SM_TOTAL>>>(
        pH, DDIM, pWThi + OFF_OUTW1, pWTlo + OFF_OUTW1, out_b1, nullptr,
        out, NOUT, NOUT, nullptr, nullptr, nullptr, nullptr, nullptr, nullptr, G, DDIM);
}